// round 9
// baseline (speedup 1.0000x reference)
#include <cuda_runtime.h>

#define BB 8
#define TTOT 100
#define NN 100000
#define MARGIN_F 0.1f
#define THRESH_F 0.5f
#define T_TILE 10
#define NTT (TTOT / T_TILE)
#define NSPLIT 32
#define CHUNK (NN / NSPLIT)             // 3125
#define NTHREADS 256
#define NITEMS (BB * NTT * NSPLIT)      // 2560
#define GRID 444                        // 3 blocks/SM * 148 SMs

// Scratch (device globals; no allocation). Zero at load; last block re-zeroes
// everything so each graph replay starts clean.
__device__ int          g_acc[BB * TTOT];
__device__ unsigned int g_done;
__device__ unsigned int g_work;

__device__ __forceinline__ float fast_sqrt(float x) {
    float r;
    asm("sqrt.approx.f32 %0, %1;" : "=f"(r) : "f"(x));
    return r;
}

__global__ void __launch_bounds__(NTHREADS, 3) fused_kernel(
    const float* __restrict__ outputs,
    const float* __restrict__ c2ws,
    const float* __restrict__ ss,
    const float* __restrict__ means,
    const float* __restrict__ scales,
    float* __restrict__ out)
{
    const int tid  = threadIdx.x;
    const int lane = tid & 31;
    const int wrp  = tid >> 5;

    __shared__ float4 sh_r[TTOT];
    __shared__ float  sh_lb[3], sh_ub[3];
    __shared__ unsigned int sh_item;

    int prev_b = -1;
    float lb0 = 0.f, lb1 = 0.f, lb2 = 0.f, ub0 = 0.f, ub1 = 0.f, ub2 = 0.f;

    for (;;) {
        if (tid == 0) sh_item = atomicAdd(&g_work, 1u);
        __syncthreads();
        unsigned int it = sh_item;
        __syncthreads();                   // protect sh_item before next write
        if (it >= NITEMS) break;

        const int b  = it / (NTT * NSPLIT);
        const int r_ = it - b * (NTT * NSPLIT);
        const int tt = r_ / NSPLIT;
        const int s  = r_ - tt * NSPLIT;
        const int tbase = tt * T_TILE;

        // ---- Prologue (only when b changes): retrajs + bounds ----
        if (b != prev_b) {
            prev_b = b;
            if (tid < TTOT) {
                const float  sb = ss[b];
                const float* o  = outputs + (b * TTOT + tid) * 3;
                const float* M  = c2ws + b * 16;
                float o0 = o[0], o1 = o[1], o2 = o[2];
                float r0 = fmaf(o0, M[0] * sb, fmaf(o1, M[1] * sb, fmaf(o2, M[2]  * sb, M[3])));
                float r1 = fmaf(o0, M[4] * sb, fmaf(o1, M[5] * sb, fmaf(o2, M[6]  * sb, M[7])));
                float r2 = fmaf(o0, M[8] * sb, fmaf(o1, M[9] * sb, fmaf(o2, M[10] * sb, M[11])));
                float rr2 = fmaf(r0, r0, fmaf(r1, r1, r2 * r2));
                sh_r[tid] = make_float4(r0, r1, r2, rr2);
            }
            __syncthreads();
            if (wrp < 3) {
                float mn = 1e30f, mx = -1e30f;
                for (int t = lane; t < TTOT; t += 32) {
                    float4 rr = sh_r[t];
                    float v = (wrp == 0) ? rr.x : ((wrp == 1) ? rr.y : rr.z);
                    mn = fminf(mn, v);
                    mx = fmaxf(mx, v);
                }
                #pragma unroll
                for (int o = 16; o > 0; o >>= 1) {
                    mn = fminf(mn, __shfl_xor_sync(0xffffffffu, mn, o));
                    mx = fmaxf(mx, __shfl_xor_sync(0xffffffffu, mx, o));
                }
                if (lane == 0) {
                    float thres = THRESH_F * ss[0];
                    sh_lb[wrp] = mn - thres;
                    sh_ub[wrp] = mx + thres;
                }
            }
            __syncthreads();
            lb0 = sh_lb[0]; lb1 = sh_lb[1]; lb2 = sh_lb[2];
            ub0 = sh_ub[0]; ub1 = sh_ub[1]; ub2 = sh_ub[2];
        }

        // ---- Register tile of T_TILE trajectory points (50 regs) ----
        float rx[T_TILE], ry[T_TILE], rz[T_TILE], C[T_TILE], acc[T_TILE];
        #pragma unroll
        for (int j = 0; j < T_TILE; j++) {
            float4 rr = sh_r[tbase + j];
            rx[j] = rr.x; ry[j] = rr.y; rz[j] = rr.z; C[j] = rr.w;
            acc[j] = 0.0f;
        }

        // ---- Main loop over this item's point chunk ----
        const int n0 = s * CHUNK;
        const int n1 = (s == NSPLIT - 1) ? NN : (n0 + CHUNK);

        #pragma unroll 2
        for (int n = n0 + tid; n < n1; n += NTHREADS) {
            float mx_ = means[n * 3 + 0];
            float my_ = means[n * 3 + 1];
            float mz_ = means[n * 3 + 2];
            float s0 = scales[n * 3 + 0];
            float s1 = scales[n * 3 + 1];
            float s2 = scales[n * 3 + 2];
            float rad = fmaxf(s0, fmaxf(s1, s2));
            bool inside = (mx_ >= lb0) & (mx_ <= ub0) &
                          (my_ >= lb1) & (my_ <= ub1) &
                          (mz_ >= lb2) & (mz_ <= ub2);
            float w  = inside ? (rad + MARGIN_F) : -1e30f;
            float px = -2.0f * mx_;
            float py = -2.0f * my_;
            float pz = -2.0f * mz_;
            float m2 = fmaf(mx_, mx_, fmaf(my_, my_, mz_ * mz_));

            #pragma unroll
            for (int j = 0; j < T_TILE; j++) {
                float d2 = C[j] + m2;
                d2 = fmaf(px, rx[j], d2);
                d2 = fmaf(py, ry[j], d2);
                d2 = fmaf(pz, rz[j], d2);
                // d2 < 0 only from rounding at dist~0; sqrt->NaN, fmaxf drops it
                float v = w - fast_sqrt(d2);
                acc[j] = fmaxf(acc[j], v);
            }
        }

        // ---- Block reduction: warp shfl max, then cross-warp via shared ----
        __shared__ float red[T_TILE][NTHREADS / 32];
        #pragma unroll
        for (int j = 0; j < T_TILE; j++) {
            float v = acc[j];
            #pragma unroll
            for (int o = 16; o > 0; o >>= 1)
                v = fmaxf(v, __shfl_xor_sync(0xffffffffu, v, o));
            if (lane == 0) red[j][wrp] = v;
        }
        __syncthreads();
        if (tid < T_TILE) {
            float v = red[tid][0];
            #pragma unroll
            for (int w = 1; w < NTHREADS / 32; w++)
                v = fmaxf(v, red[tid][w]);
            if (v > 0.0f)
                atomicMax(&g_acc[b * TTOT + tbase + tid], __float_as_int(v));
        }
        __syncthreads();                   // red[] reuse safety on next item
    }

    // ---- Last finishing block: final sum, write scalar, reset state ----
    __shared__ bool isLast;
    __threadfence();
    if (tid == 0) {
        unsigned int prev = atomicAdd(&g_done, 1u);
        isLast = (prev == (unsigned int)(GRID - 1));
    }
    __syncthreads();
    if (isLast) {
        __shared__ float sh[NTHREADS];
        float sum = 0.0f;
        for (int i = tid; i < BB * TTOT; i += NTHREADS) {
            sum += __int_as_float(g_acc[i]);
            g_acc[i] = 0;                  // reset for next replay
        }
        sh[tid] = sum;
        __syncthreads();
        for (int o = NTHREADS / 2; o > 0; o >>= 1) {
            if (tid < o) sh[tid] += sh[tid + o];
            __syncthreads();
        }
        if (tid == 0) {
            out[0] = sh[0] / (float)(BB * TTOT);
            g_work = 0;                    // reset for next replay
            g_done = 0;
        }
    }
}

extern "C" void kernel_launch(void* const* d_in, const int* in_sizes, int n_in,
                              void* d_out, int out_size) {
    const float* outputs = (const float*)d_in[0];  // (8,100,3)
    const float* c2ws    = (const float*)d_in[1];  // (8,4,4)
    const float* ss      = (const float*)d_in[2];  // (8,)
    const float* means   = (const float*)d_in[3];  // (100000,3)
    const float* scales  = (const float*)d_in[4];  // (100000,3)
    float* out = (float*)d_out;

    fused_kernel<<<GRID, NTHREADS>>>(outputs, c2ws, ss, means, scales, out);
}

// round 10
// speedup vs baseline: 1.0370x; 1.0370x over previous
#include <cuda_runtime.h>

#define BB 8
#define TTOT 100
#define NN 100000
#define MARGIN_F 0.1f
#define THRESH_F 0.5f
#define T_TILE 10
#define NTT (TTOT / T_TILE)
#define NSPLIT 32
#define CHUNK (NN / NSPLIT)             // 3125
#define NTHREADS 256
#define NITEMS (BB * NTT * NSPLIT)      // 2560
#define GRID 444                        // 3 blocks/SM * 148 SMs (all resident)
#define PTS_PER_BLK ((NN + GRID - 1) / GRID)   // 226

// Scratch (device globals; no allocation). Zero at load; last block re-zeroes
// all mutable state so each graph replay starts clean.
__device__ float4       g_retraj[BB * TTOT];   // (rx,ry,rz,r2)
__device__ float        g_lb[BB][3], g_ub[BB][3];
__device__ float4       g_tab[NN];             // (-2x,-2y,-2z,m2)
__device__ float        g_w[BB][NN];           // rad+MARGIN or -1e30
__device__ int          g_acc[BB * TTOT];
__device__ unsigned int g_done, g_work, g_barA, g_barB;

__device__ __forceinline__ float fast_sqrt(float x) {
    float r;
    asm("sqrt.approx.f32 %0, %1;" : "=f"(r) : "f"(x));
    return r;
}

__device__ __forceinline__ void grid_barrier(unsigned int* bar, int tid) {
    __threadfence();
    __syncthreads();
    if (tid == 0) {
        atomicAdd(bar, 1u);
        while (*((volatile unsigned int*)bar) < GRID) __nanosleep(64);
    }
    __syncthreads();
    __threadfence();
}

__global__ void __launch_bounds__(NTHREADS, 3) fused_kernel(
    const float* __restrict__ outputs,
    const float* __restrict__ c2ws,
    const float* __restrict__ ss,
    const float* __restrict__ means,
    const float* __restrict__ scales,
    float* __restrict__ out)
{
    const int tid  = threadIdx.x;
    const int lane = tid & 31;
    const int wrp  = tid >> 5;

    // ---- Phase A: blocks 0..7 compute retrajs + bounds for b = blockIdx.x ----
    if (blockIdx.x < BB) {
        const int b = blockIdx.x;
        __shared__ float4 sh_r[TTOT];
        if (tid < TTOT) {
            const float  sb = ss[b];
            const float* o  = outputs + (b * TTOT + tid) * 3;
            const float* M  = c2ws + b * 16;
            float o0 = o[0], o1 = o[1], o2 = o[2];
            float r0 = fmaf(o0, M[0] * sb, fmaf(o1, M[1] * sb, fmaf(o2, M[2]  * sb, M[3])));
            float r1 = fmaf(o0, M[4] * sb, fmaf(o1, M[5] * sb, fmaf(o2, M[6]  * sb, M[7])));
            float r2 = fmaf(o0, M[8] * sb, fmaf(o1, M[9] * sb, fmaf(o2, M[10] * sb, M[11])));
            float rr2 = fmaf(r0, r0, fmaf(r1, r1, r2 * r2));
            float4 v = make_float4(r0, r1, r2, rr2);
            g_retraj[b * TTOT + tid] = v;
            sh_r[tid] = v;
        }
        __syncthreads();
        if (wrp < 3) {
            float mn = 1e30f, mx = -1e30f;
            for (int t = lane; t < TTOT; t += 32) {
                float4 rr = sh_r[t];
                float v = (wrp == 0) ? rr.x : ((wrp == 1) ? rr.y : rr.z);
                mn = fminf(mn, v);
                mx = fmaxf(mx, v);
            }
            #pragma unroll
            for (int o = 16; o > 0; o >>= 1) {
                mn = fminf(mn, __shfl_xor_sync(0xffffffffu, mn, o));
                mx = fmaxf(mx, __shfl_xor_sync(0xffffffffu, mx, o));
            }
            if (lane == 0) {
                float thres = THRESH_F * ss[0];
                g_lb[b][wrp] = mn - thres;
                g_ub[b][wrp] = mx + thres;
            }
        }
    }
    grid_barrier(&g_barA, tid);

    // ---- Phase B: build point table + per-b masked w (each point ONCE) ----
    {
        __shared__ float sLB[BB][3], sUB[BB][3];
        if (tid < BB * 3) {
            int b = tid / 3, e = tid - b * 3;
            sLB[b][e] = g_lb[b][e];
            sUB[b][e] = g_ub[b][e];
        }
        __syncthreads();
        const int p0 = blockIdx.x * PTS_PER_BLK;
        const int p1 = (p0 + PTS_PER_BLK > NN) ? NN : (p0 + PTS_PER_BLK);
        for (int n = p0 + tid; n < p1; n += NTHREADS) {
            float x = means[n * 3 + 0];
            float y = means[n * 3 + 1];
            float z = means[n * 3 + 2];
            float s0 = scales[n * 3 + 0];
            float s1 = scales[n * 3 + 1];
            float s2 = scales[n * 3 + 2];
            float rad = fmaxf(s0, fmaxf(s1, s2));
            float m2 = fmaf(x, x, fmaf(y, y, z * z));
            g_tab[n] = make_float4(-2.0f * x, -2.0f * y, -2.0f * z, m2);
            float wbase = rad + MARGIN_F;
            #pragma unroll
            for (int b = 0; b < BB; b++) {
                bool inside = (x >= sLB[b][0]) & (x <= sUB[b][0]) &
                              (y >= sLB[b][1]) & (y <= sUB[b][1]) &
                              (z >= sLB[b][2]) & (z <= sUB[b][2]);
                g_w[b][n] = inside ? wbase : -1e30f;
            }
        }
    }
    grid_barrier(&g_barB, tid);

    // ---- Phase C: persistent work-stealing over (b, tt, s) items ----
    __shared__ unsigned int sh_item;
    __shared__ float red[T_TILE][NTHREADS / 32];
    for (;;) {
        if (tid == 0) sh_item = atomicAdd(&g_work, 1u);
        __syncthreads();
        unsigned int it = sh_item;
        __syncthreads();
        if (it >= NITEMS) break;

        const int b  = it / (NTT * NSPLIT);
        const int r_ = it - b * (NTT * NSPLIT);
        const int tt = r_ / NSPLIT;
        const int s  = r_ - tt * NSPLIT;
        const int tbase = tt * T_TILE;

        float rx[T_TILE], ry[T_TILE], rz[T_TILE], C[T_TILE], acc[T_TILE];
        #pragma unroll
        for (int j = 0; j < T_TILE; j++) {
            float4 rr = g_retraj[b * TTOT + tbase + j];
            rx[j] = rr.x; ry[j] = rr.y; rz[j] = rr.z; C[j] = rr.w;
            acc[j] = 0.0f;
        }

        const float* __restrict__ wv = g_w[b];
        const int n0 = s * CHUNK;
        const int n1 = (s == NSPLIT - 1) ? NN : (n0 + CHUNK);

        #pragma unroll 2
        for (int n = n0 + tid; n < n1; n += NTHREADS) {
            float4 p = g_tab[n];
            float  w = wv[n];
            #pragma unroll
            for (int j = 0; j < T_TILE; j++) {
                float d2 = C[j] + p.w;
                d2 = fmaf(p.x, rx[j], d2);
                d2 = fmaf(p.y, ry[j], d2);
                d2 = fmaf(p.z, rz[j], d2);
                // d2<0 only from rounding at dist~0: sqrt->NaN, fmaxf drops it
                float v = w - fast_sqrt(d2);
                acc[j] = fmaxf(acc[j], v);
            }
        }

        #pragma unroll
        for (int j = 0; j < T_TILE; j++) {
            float v = acc[j];
            #pragma unroll
            for (int o = 16; o > 0; o >>= 1)
                v = fmaxf(v, __shfl_xor_sync(0xffffffffu, v, o));
            if (lane == 0) red[j][wrp] = v;
        }
        __syncthreads();
        if (tid < T_TILE) {
            float v = red[tid][0];
            #pragma unroll
            for (int w = 1; w < NTHREADS / 32; w++)
                v = fmaxf(v, red[tid][w]);
            if (v > 0.0f)
                atomicMax(&g_acc[b * TTOT + tbase + tid], __float_as_int(v));
        }
        __syncthreads();
    }

    // ---- Last finishing block: final sum, write scalar, reset all state ----
    __shared__ bool isLast;
    __threadfence();
    if (tid == 0) {
        unsigned int prev = atomicAdd(&g_done, 1u);
        isLast = (prev == (unsigned int)(GRID - 1));
    }
    __syncthreads();
    if (isLast) {
        __shared__ float sh[NTHREADS];
        float sum = 0.0f;
        for (int i = tid; i < BB * TTOT; i += NTHREADS) {
            sum += __int_as_float(g_acc[i]);
            g_acc[i] = 0;
        }
        sh[tid] = sum;
        __syncthreads();
        for (int o = NTHREADS / 2; o > 0; o >>= 1) {
            if (tid < o) sh[tid] += sh[tid + o];
            __syncthreads();
        }
        if (tid == 0) {
            out[0] = sh[0] / (float)(BB * TTOT);
            g_work = 0;
            g_done = 0;
            g_barA = 0;
            g_barB = 0;
        }
    }
}

extern "C" void kernel_launch(void* const* d_in, const int* in_sizes, int n_in,
                              void* d_out, int out_size) {
    const float* outputs = (const float*)d_in[0];  // (8,100,3)
    const float* c2ws    = (const float*)d_in[1];  // (8,4,4)
    const float* ss      = (const float*)d_in[2];  // (8,)
    const float* means   = (const float*)d_in[3];  // (100000,3)
    const float* scales  = (const float*)d_in[4];  // (100000,3)
    float* out = (float*)d_out;

    fused_kernel<<<GRID, NTHREADS>>>(outputs, c2ws, ss, means, scales, out);
}